// round 13
// baseline (speedup 1.0000x reference)
#include <cuda_runtime.h>
#include <cuda_fp16.h>
#include <cstdint>

// Fused NeRF MLP: [N,6] ->128 ->128 ->128 -> [N,4]
// L1: m16n8k8 fp16->f32 accum.  L4: m16n8k16 fp16->f32 accum.
// L2/L3: m16n8k16 with F16 ACCUMULATORS -- 4 independent K=32 chunk chains,
// combined by an f16x2 add tree + packed bias + relu. Chunk results are
// already in a-fragment layout: no cvt in hidden layers at all.
// Each warp: 32 points as two m16 rowsets; weight LDS.128 feeds 4 MMAs.
// Software-pipelined x prefetch; no barriers in the tile loop.

#define NTHR   256      // 8 warps
#define TILE_M 256      // points per CTA tile (32 per warp)

#define PK_BYTES (16*4*32*16)      // 32 KB per hidden layer
#define SM_P2   0
#define SM_P3   (SM_P2 + PK_BYTES)
#define SM_P1   (SM_P3 + PK_BYTES)     // 512 * 4B  = 2048
#define SM_P4   (SM_P1 + 2048)         // 256 * 8B  = 2048
#define SM_B1   (SM_P4 + 2048)         // 512
#define SM_B4   (SM_B1 + 512)          // 64
#define SM_B2P  (SM_B4 + 64)           // 64 * 4B packed f16x2 bias
#define SM_B3P  (SM_B2P + 256)         // 256
#define SMEM_TOTAL (SM_B3P + 256)

static __device__ __forceinline__ void mma_f16(float* c, const uint32_t* a,
                                               uint32_t b0, uint32_t b1) {
    asm volatile(
        "mma.sync.aligned.m16n8k16.row.col.f32.f16.f16.f32 "
        "{%0,%1,%2,%3},{%4,%5,%6,%7},{%8,%9},{%0,%1,%2,%3};"
        : "+f"(c[0]), "+f"(c[1]), "+f"(c[2]), "+f"(c[3])
        : "r"(a[0]), "r"(a[1]), "r"(a[2]), "r"(a[3]), "r"(b0), "r"(b1));
}
static __device__ __forceinline__ void mma_f16k8(float* c, uint32_t a0,
                                                 uint32_t a1, uint32_t b0) {
    asm volatile(
        "mma.sync.aligned.m16n8k8.row.col.f32.f16.f16.f32 "
        "{%0,%1,%2,%3},{%4,%5},{%6},{%0,%1,%2,%3};"
        : "+f"(c[0]), "+f"(c[1]), "+f"(c[2]), "+f"(c[3])
        : "r"(a0), "r"(a1), "r"(b0));
}
// f16-accumulator MMA: D/C are 2 regs of packed f16x2
static __device__ __forceinline__ void mma_h16(uint32_t* c, const uint32_t* a,
                                               uint32_t b0, uint32_t b1) {
    asm volatile(
        "mma.sync.aligned.m16n8k16.row.col.f16.f16.f16.f16 "
        "{%0,%1},{%2,%3,%4,%5},{%6,%7},{%0,%1};"
        : "+r"(c[0]), "+r"(c[1])
        : "r"(a[0]), "r"(a[1]), "r"(a[2]), "r"(a[3]), "r"(b0), "r"(b1));
}

static __device__ __forceinline__ uint32_t pack_f16(float v0, float v1) {
    uint32_t r;
    asm("cvt.rn.f16x2.f32 %0, %1, %2;" : "=r"(r) : "f"(v1), "f"(v0));
    return r;
}
static __device__ __forceinline__ uint32_t hadd2(uint32_t x, uint32_t y) {
    uint32_t r;
    asm("add.f16x2 %0, %1, %2;" : "=r"(r) : "r"(x), "r"(y));
    return r;
}
static __device__ __forceinline__ uint32_t relu2(uint32_t v) {
    uint32_t r;
    asm("max.f16x2 %0, %1, %2;" : "=r"(r) : "r"(v), "r"(0u));
    return r;
}

// relu + pack one finished f32 n-tile (c[4]) into a-frag slots (L1 only)
static __device__ __forceinline__ void pack_tile(uint32_t* a, int t,
                                                 const float* c) {
    const int K = t >> 1;
    const int o = (t & 1) ? (4 * K + 2) : (4 * K);
    a[o]     = relu2(pack_f16(c[0], c[1]));
    a[o + 1] = relu2(pack_f16(c[2], c[3]));
}

// one 128->128 hidden-layer n-tile, f16 accumulators, both rowsets.
// 4 independent K=32 chunk chains per rowset; tree-combined in f16x2.
// Output regs are already a-frag layout (c0={d[g][jc],d[g][jc+1]}, c1=row g+8).
static __device__ __forceinline__ void hidden_tile16(
    const uint32_t* aA, const uint32_t* aB, const uint4* pk, int t,
    uint32_t bp, uint32_t* oA, uint32_t* oB)
{
    uint32_t chA[4][2], chB[4][2];
    #pragma unroll
    for (int Kp = 0; Kp < 4; Kp++) {
        const uint4 b = pk[(t * 4 + Kp) * 32];
        chA[Kp][0] = 0u; chA[Kp][1] = 0u;
        chB[Kp][0] = 0u; chB[Kp][1] = 0u;
        mma_h16(chA[Kp], aA + 8 * Kp,     b.x, b.y);
        mma_h16(chB[Kp], aB + 8 * Kp,     b.x, b.y);
        mma_h16(chA[Kp], aA + 8 * Kp + 4, b.z, b.w);
        mma_h16(chB[Kp], aB + 8 * Kp + 4, b.z, b.w);
    }
    const int K = t >> 1;
    const int o = (t & 1) ? (4 * K + 2) : (4 * K);
    oA[o]     = relu2(hadd2(hadd2(hadd2(chA[0][0], chA[1][0]),
                                  hadd2(chA[2][0], chA[3][0])), bp));
    oA[o + 1] = relu2(hadd2(hadd2(hadd2(chA[0][1], chA[1][1]),
                                  hadd2(chA[2][1], chA[3][1])), bp));
    oB[o]     = relu2(hadd2(hadd2(hadd2(chB[0][0], chB[1][0]),
                                  hadd2(chB[2][0], chB[3][0])), bp));
    oB[o + 1] = relu2(hadd2(hadd2(hadd2(chB[0][1], chB[1][1]),
                                  hadd2(chB[2][1], chB[3][1])), bp));
}

__global__ __launch_bounds__(NTHR, 1)
void nerf_mma_kernel(const float* __restrict__ x,
                     const float* __restrict__ W1, const float* __restrict__ b1,
                     const float* __restrict__ W2, const float* __restrict__ b2,
                     const float* __restrict__ W3, const float* __restrict__ b3,
                     const float* __restrict__ W4, const float* __restrict__ b4,
                     float* __restrict__ out, int ntiles)
{
    extern __shared__ char smem[];
    uint4*    sP2  = (uint4*)(smem + SM_P2);
    uint4*    sP3  = (uint4*)(smem + SM_P3);
    uint32_t* sP1  = (uint32_t*)(smem + SM_P1);
    uint2*    sP4  = (uint2*)(smem + SM_P4);
    float*    sB1  = (float*)(smem + SM_B1);
    float*    sB4  = (float*)(smem + SM_B4);
    uint32_t* sB2p = (uint32_t*)(smem + SM_B2P);
    uint32_t* sB3p = (uint32_t*)(smem + SM_B3P);

    const int tid  = threadIdx.x;
    const int warp = tid >> 5;
    const int lane = tid & 31;
    const int g    = lane >> 2;
    const int tig  = lane & 3;

    // ---- one-time: packed fp16 weight fragment records ----
    for (int idx = tid; idx < 2 * 2048; idx += NTHR) {     // W2 / W3
        const int layer = idx >> 11;
        const int e     = idx & 2047;
        const int t  = e >> 7;
        const int Kp = (e >> 5) & 3;
        const int ln = e & 31;
        const int j  = 8 * t + (ln >> 2);
        const int k0 = 32 * Kp + 2 * (ln & 3);
        const float* W = layer ? W3 : W2;
        uint4 rec;
        rec.x = pack_f16(W[j * 128 + k0],      W[j * 128 + k0 + 1]);
        rec.y = pack_f16(W[j * 128 + k0 + 8],  W[j * 128 + k0 + 9]);
        rec.z = pack_f16(W[j * 128 + k0 + 16], W[j * 128 + k0 + 17]);
        rec.w = pack_f16(W[j * 128 + k0 + 24], W[j * 128 + k0 + 25]);
        (layer ? sP3 : sP2)[e] = rec;
    }
    for (int idx = tid; idx < 512; idx += NTHR) {          // W1 (K=6 pad k8)
        const int t  = idx >> 5;
        const int ln = idx & 31;
        const int j  = 8 * t + (ln >> 2);
        const int k0 = 2 * (ln & 3);
        float v0 = (k0     < 6) ? W1[j * 6 + k0]     : 0.f;
        float v1 = (k0 + 1 < 6) ? W1[j * 6 + k0 + 1] : 0.f;
        sP1[idx] = pack_f16(v0, v1);
    }
    for (int idx = tid; idx < 256; idx += NTHR) {          // W4 (n=4 pad 8)
        const int K  = idx >> 5;
        const int ln = idx & 31;
        const int n  = ln >> 2;
        const int k0 = 16 * K + 2 * (ln & 3);
        uint2 rec;
        if (n < 4) {
            const float* wr = W4 + n * 128 + k0;
            rec.x = pack_f16(wr[0], wr[1]);
            rec.y = pack_f16(wr[8], wr[9]);
        } else rec.x = rec.y = 0u;
        sP4[idx] = rec;
    }
    if (tid < 128) sB1[tid] = b1[tid];
    if (tid < 8)   sB4[tid] = (tid < 4) ? b4[tid] : 0.f;
    if (tid < 64) {                          // packed f16x2 bias pairs
        const int t  = tid >> 2;
        const int tg = tid & 3;
        const int jc = 8 * t + 2 * tg;
        sB2p[tid] = pack_f16(b2[jc], b2[jc + 1]);
        sB3p[tid] = pack_f16(b3[jc], b3[jc + 1]);
    }
    __syncthreads();

    const uint4* pk2 = sP2 + lane;
    const uint4* pk3 = sP3 + lane;
    const uint32_t* pk1 = sP1 + lane;
    const uint2* pk4 = sP4 + lane;

    const int pw = warp * 32;
    const int xk0 = 2 * tig;

    // ---- x prefetch prologue (first tile) ----
    int tile = blockIdx.x;
    float2 vx0, vx1, vx2, vx3;
    vx0 = vx1 = vx2 = vx3 = make_float2(0.f, 0.f);
    if (tile < ntiles && tig < 3) {
        const long long b0 = (long long)tile * TILE_M;
        vx0 = *(const float2*)(x + (b0 + pw + g)      * 6 + xk0);
        vx1 = *(const float2*)(x + (b0 + pw + g + 8)  * 6 + xk0);
        vx2 = *(const float2*)(x + (b0 + pw + g + 16) * 6 + xk0);
        vx3 = *(const float2*)(x + (b0 + pw + g + 24) * 6 + xk0);
    }

    for (; tile < ntiles; tile += gridDim.x) {
        const long long base = (long long)tile * TILE_M;
        // thread's 4 points: rows g, g+8 (rowset A), g+16, g+24 (rowset B)

        uint32_t aA[32], aB[32];
        uint32_t aA2[32], aB2[32];

        // ---- pack prefetched x into fp16 A-frags (k 0..5, rest zero) ----
        const uint32_t xA0 = (tig < 3) ? pack_f16(vx0.x, vx0.y) : 0u;
        const uint32_t xA1 = (tig < 3) ? pack_f16(vx1.x, vx1.y) : 0u;
        const uint32_t xB0 = (tig < 3) ? pack_f16(vx2.x, vx2.y) : 0u;
        const uint32_t xB1 = (tig < 3) ? pack_f16(vx3.x, vx3.y) : 0u;

        // ---- layer 1: m16n8k8, f32 accum, two n-tiles interleaved ----
        #pragma unroll
        for (int tp = 0; tp < 8; tp++) {
            const int t0 = 2 * tp, t1 = 2 * tp + 1;
            const int jc0 = 8 * t0 + 2 * tig;
            const int jc1 = 8 * t1 + 2 * tig;
            const uint32_t b0 = pk1[t0 * 32];
            const uint32_t b1v = pk1[t1 * 32];
            float cA0[4], cB0[4], cA1[4], cB1[4];
            cA0[0] = cA0[2] = cB0[0] = cB0[2] = sB1[jc0];
            cA0[1] = cA0[3] = cB0[1] = cB0[3] = sB1[jc0 + 1];
            cA1[0] = cA1[2] = cB1[0] = cB1[2] = sB1[jc1];
            cA1[1] = cA1[3] = cB1[1] = cB1[3] = sB1[jc1 + 1];
            mma_f16k8(cA0, xA0, xA1, b0);
            mma_f16k8(cB0, xB0, xB1, b0);
            mma_f16k8(cA1, xA0, xA1, b1v);
            mma_f16k8(cB1, xB0, xB1, b1v);
            pack_tile(aA, t0, cA0);
            pack_tile(aB, t0, cB0);
            pack_tile(aA, t1, cA1);
            pack_tile(aB, t1, cB1);
        }

        // ---- layer 2 (f16 accum, chunked) ----
        #pragma unroll
        for (int t = 0; t < 16; t++)
            hidden_tile16(aA, aB, pk2, t, sB2p[t * 4 + tig], aA2, aB2);

        // ---- prefetch next tile's x (covered by L3+L4 latency) ----
        {
            const int nt = tile + gridDim.x;
            if (nt < ntiles && tig < 3) {
                const long long nb = (long long)nt * TILE_M;
                vx0 = *(const float2*)(x + (nb + pw + g)      * 6 + xk0);
                vx1 = *(const float2*)(x + (nb + pw + g + 8)  * 6 + xk0);
                vx2 = *(const float2*)(x + (nb + pw + g + 16) * 6 + xk0);
                vx3 = *(const float2*)(x + (nb + pw + g + 24) * 6 + xk0);
            }
        }

        // ---- layer 3 (f16 accum, chunked; packs back into aA/aB) ----
        #pragma unroll
        for (int t = 0; t < 16; t++)
            hidden_tile16(aA2, aB2, pk3, t, sB3p[t * 4 + tig], aA, aB);

        // ---- layer 4: f32 accum, n=8 (4 valid), accumulate 8 k-tiles ----
        {
            float cA[4], cB[4];
            const float bb0 = (tig < 2) ? sB4[2 * tig]     : 0.f;
            const float bb1 = (tig < 2) ? sB4[2 * tig + 1] : 0.f;
            cA[0] = cA[2] = cB[0] = cB[2] = bb0;
            cA[1] = cA[3] = cB[1] = cB[3] = bb1;
            #pragma unroll
            for (int K = 0; K < 8; K++) {
                uint2 b = pk4[K * 32];
                mma_f16(cA, aA + 4 * K, b.x, b.y);
                mma_f16(cB, aB + 4 * K, b.x, b.y);
            }
            if (tig < 2) {
                float* o0 = out + (base + pw + g)      * 4 + 2 * tig;
                float* o1 = out + (base + pw + g + 8)  * 4 + 2 * tig;
                float* o2 = out + (base + pw + g + 16) * 4 + 2 * tig;
                float* o3 = out + (base + pw + g + 24) * 4 + 2 * tig;
                *(float2*)o0 = make_float2(cA[0], cA[1]);
                *(float2*)o1 = make_float2(cA[2], cA[3]);
                *(float2*)o2 = make_float2(cB[0], cB[1]);
                *(float2*)o3 = make_float2(cB[2], cB[3]);
            }
        }
        // no per-tile shared state -> no barriers
    }
}

extern "C" void kernel_launch(void* const* d_in, const int* in_sizes, int n_in,
                              void* d_out, int out_size)
{
    const float* x  = (const float*)d_in[0];
    const float* W1 = (const float*)d_in[1];
    const float* b1 = (const float*)d_in[2];
    const float* W2 = (const float*)d_in[3];
    const float* b2 = (const float*)d_in[4];
    const float* W3 = (const float*)d_in[5];
    const float* b3 = (const float*)d_in[6];
    const float* W4 = (const float*)d_in[7];
    const float* b4 = (const float*)d_in[8];
    float* out = (float*)d_out;

    const int n = in_sizes[0] / 6;
    const int ntiles = n / TILE_M;          // 4096
    int grid = 148;
    if (grid > ntiles) grid = ntiles;

    cudaFuncSetAttribute(nerf_mma_kernel,
                         cudaFuncAttributeMaxDynamicSharedMemorySize, SMEM_TOTAL);
    nerf_mma_kernel<<<grid, NTHR, SMEM_TOTAL>>>(
        x, W1, b1, W2, b2, W3, b3, W4, b4, out, ntiles);
}

// round 14
// speedup vs baseline: 1.2092x; 1.2092x over previous
#include <cuda_runtime.h>
#include <cuda_fp16.h>
#include <cstdint>

// Fused NeRF MLP: [N,6] ->128 ->128 ->128 -> [N,4]
// ALL four layers on mma.sync fp16 (f32 accum) -- R12 structure (plateau of
// the mma.sync path): pairs of n-tiles per inner body, weight LDS.128 feeds
// 4 MMAs, software-pipelined x prefetch, activations chained in registers.
// This round: persistent grid sized to the ACTUAL SM count (GB300 = 152,
// not 148) and pure 32-bit addressing.

#define NTHR   256      // 8 warps
#define TILE_M 256      // points per CTA tile (32 per warp)

#define PK_BYTES (16*4*32*16)      // 32 KB per hidden layer
#define SM_P2   0
#define SM_P3   (SM_P2 + PK_BYTES)
#define SM_P1   (SM_P3 + PK_BYTES)     // 512 * 4B  = 2048
#define SM_P4   (SM_P1 + 2048)         // 256 * 8B  = 2048
#define SM_B1   (SM_P4 + 2048)         // 512
#define SM_B2   (SM_B1 + 512)
#define SM_B3   (SM_B2 + 512)
#define SM_B4   (SM_B3 + 512)          // 64
#define SMEM_TOTAL (SM_B4 + 64)

static __device__ __forceinline__ void mma_f16(float* c, const uint32_t* a,
                                               uint32_t b0, uint32_t b1) {
    asm volatile(
        "mma.sync.aligned.m16n8k16.row.col.f32.f16.f16.f32 "
        "{%0,%1,%2,%3},{%4,%5,%6,%7},{%8,%9},{%0,%1,%2,%3};"
        : "+f"(c[0]), "+f"(c[1]), "+f"(c[2]), "+f"(c[3])
        : "r"(a[0]), "r"(a[1]), "r"(a[2]), "r"(a[3]), "r"(b0), "r"(b1));
}
static __device__ __forceinline__ void mma_f16k8(float* c, uint32_t a0,
                                                 uint32_t a1, uint32_t b0) {
    asm volatile(
        "mma.sync.aligned.m16n8k8.row.col.f32.f16.f16.f32 "
        "{%0,%1,%2,%3},{%4,%5},{%6},{%0,%1,%2,%3};"
        : "+f"(c[0]), "+f"(c[1]), "+f"(c[2]), "+f"(c[3])
        : "r"(a0), "r"(a1), "r"(b0));
}

static __device__ __forceinline__ uint32_t pack_f16(float v0, float v1) {
    uint32_t r;
    asm("cvt.rn.f16x2.f32 %0, %1, %2;" : "=r"(r) : "f"(v1), "f"(v0));
    return r;
}
// relu on packed f16x2 (cvt is monotone: max-after-cvt == cvt-after-max)
static __device__ __forceinline__ uint32_t relu2(uint32_t v) {
    uint32_t r;
    asm("max.f16x2 %0, %1, %2;" : "=r"(r) : "r"(v), "r"(0u));
    return r;
}

// pack one finished n-tile (c[4]) into a-frag slots for k-tile K=t>>1, relu'd
static __device__ __forceinline__ void pack_tile(uint32_t* a, int t,
                                                 const float* c) {
    const int K = t >> 1;
    const int o = (t & 1) ? (4 * K + 2) : (4 * K);
    a[o]     = relu2(pack_f16(c[0], c[1]));
    a[o + 1] = relu2(pack_f16(c[2], c[3]));
}

// two hidden-layer n-tiles (t0=2tp, t1=2tp+1) for both rowsets:
// 4 independent accumulator chains, same-chain HMMA distance = 4.
static __device__ __forceinline__ void hidden_tile_pair(
    const uint32_t* aA, const uint32_t* aB, const uint4* pk, int tp,
    const float* bias, int tig, uint32_t* oA, uint32_t* oB)
{
    const int t0 = 2 * tp, t1 = 2 * tp + 1;
    const int jc0 = 8 * t0 + 2 * tig;
    const int jc1 = 8 * t1 + 2 * tig;
    float cA0[4], cB0[4], cA1[4], cB1[4];
    cA0[0] = cA0[2] = cB0[0] = cB0[2] = bias[jc0];
    cA0[1] = cA0[3] = cB0[1] = cB0[3] = bias[jc0 + 1];
    cA1[0] = cA1[2] = cB1[0] = cB1[2] = bias[jc1];
    cA1[1] = cA1[3] = cB1[1] = cB1[3] = bias[jc1 + 1];

    #pragma unroll
    for (int Kp = 0; Kp < 4; Kp++) {
        const uint4 b0 = pk[(t0 * 4 + Kp) * 32];
        const uint4 b1 = pk[(t1 * 4 + Kp) * 32];
        mma_f16(cA0, aA + 8 * Kp,     b0.x, b0.y);
        mma_f16(cB0, aB + 8 * Kp,     b0.x, b0.y);
        mma_f16(cA1, aA + 8 * Kp,     b1.x, b1.y);
        mma_f16(cB1, aB + 8 * Kp,     b1.x, b1.y);
        mma_f16(cA0, aA + 8 * Kp + 4, b0.z, b0.w);
        mma_f16(cB0, aB + 8 * Kp + 4, b0.z, b0.w);
        mma_f16(cA1, aA + 8 * Kp + 4, b1.z, b1.w);
        mma_f16(cB1, aB + 8 * Kp + 4, b1.z, b1.w);
    }
    pack_tile(oA, t0, cA0);
    pack_tile(oB, t0, cB0);
    pack_tile(oA, t1, cA1);
    pack_tile(oB, t1, cB1);
}

__global__ __launch_bounds__(NTHR, 1)
void nerf_mma_kernel(const float* __restrict__ x,
                     const float* __restrict__ W1, const float* __restrict__ b1,
                     const float* __restrict__ W2, const float* __restrict__ b2,
                     const float* __restrict__ W3, const float* __restrict__ b3,
                     const float* __restrict__ W4, const float* __restrict__ b4,
                     float* __restrict__ out, int ntiles)
{
    extern __shared__ char smem[];
    uint4*    sP2 = (uint4*)(smem + SM_P2);
    uint4*    sP3 = (uint4*)(smem + SM_P3);
    uint32_t* sP1 = (uint32_t*)(smem + SM_P1);
    uint2*    sP4 = (uint2*)(smem + SM_P4);
    float* sB1 = (float*)(smem + SM_B1);
    float* sB2 = (float*)(smem + SM_B2);
    float* sB3 = (float*)(smem + SM_B3);
    float* sB4 = (float*)(smem + SM_B4);

    const int tid  = threadIdx.x;
    const int warp = tid >> 5;
    const int lane = tid & 31;
    const int g    = lane >> 2;
    const int tig  = lane & 3;

    // ---- one-time: packed fp16 weight fragment records ----
    for (int idx = tid; idx < 2 * 2048; idx += NTHR) {     // W2 / W3
        const int layer = idx >> 11;
        const int e     = idx & 2047;
        const int t  = e >> 7;
        const int Kp = (e >> 5) & 3;
        const int ln = e & 31;
        const int j  = 8 * t + (ln >> 2);
        const int k0 = 32 * Kp + 2 * (ln & 3);
        const float* W = layer ? W3 : W2;
        uint4 rec;
        rec.x = pack_f16(W[j * 128 + k0],      W[j * 128 + k0 + 1]);
        rec.y = pack_f16(W[j * 128 + k0 + 8],  W[j * 128 + k0 + 9]);
        rec.z = pack_f16(W[j * 128 + k0 + 16], W[j * 128 + k0 + 17]);
        rec.w = pack_f16(W[j * 128 + k0 + 24], W[j * 128 + k0 + 25]);
        (layer ? sP3 : sP2)[e] = rec;
    }
    for (int idx = tid; idx < 512; idx += NTHR) {          // W1 (K=6 pad k8)
        const int t  = idx >> 5;
        const int ln = idx & 31;
        const int j  = 8 * t + (ln >> 2);
        const int k0 = 2 * (ln & 3);
        float v0 = (k0     < 6) ? W1[j * 6 + k0]     : 0.f;
        float v1 = (k0 + 1 < 6) ? W1[j * 6 + k0 + 1] : 0.f;
        sP1[idx] = pack_f16(v0, v1);
    }
    for (int idx = tid; idx < 256; idx += NTHR) {          // W4 (n=4 pad 8)
        const int K  = idx >> 5;
        const int ln = idx & 31;
        const int n  = ln >> 2;
        const int k0 = 16 * K + 2 * (ln & 3);
        uint2 rec;
        if (n < 4) {
            const float* wr = W4 + n * 128 + k0;
            rec.x = pack_f16(wr[0], wr[1]);
            rec.y = pack_f16(wr[8], wr[9]);
        } else rec.x = rec.y = 0u;
        sP4[idx] = rec;
    }
    if (tid < 128) { sB1[tid] = b1[tid]; sB2[tid] = b2[tid]; sB3[tid] = b3[tid]; }
    if (tid < 8)   sB4[tid] = (tid < 4) ? b4[tid] : 0.f;
    __syncthreads();

    const uint4* pk2 = sP2 + lane;
    const uint4* pk3 = sP3 + lane;
    const uint32_t* pk1 = sP1 + lane;
    const uint2* pk4 = sP4 + lane;

    const int pw = warp * 32;
    const int xk0 = 2 * tig;

    // ---- x prefetch prologue (first tile); 32-bit offsets throughout ----
    int tile = blockIdx.x;
    float2 vx0, vx1, vx2, vx3;
    vx0 = vx1 = vx2 = vx3 = make_float2(0.f, 0.f);
    if (tile < ntiles && tig < 3) {
        const int b0 = tile * TILE_M;
        vx0 = *(const float2*)(x + (b0 + pw + g)      * 6 + xk0);
        vx1 = *(const float2*)(x + (b0 + pw + g + 8)  * 6 + xk0);
        vx2 = *(const float2*)(x + (b0 + pw + g + 16) * 6 + xk0);
        vx3 = *(const float2*)(x + (b0 + pw + g + 24) * 6 + xk0);
    }

    for (; tile < ntiles; tile += gridDim.x) {
        const int base = tile * TILE_M;
        // thread's 4 points: rows g, g+8 (rowset A), g+16, g+24 (rowset B)

        uint32_t aA[32], aB[32];
        uint32_t aA2[32], aB2[32];

        // ---- pack prefetched x into fp16 A-frags (k 0..5, rest zero) ----
        const uint32_t xA0 = (tig < 3) ? pack_f16(vx0.x, vx0.y) : 0u;
        const uint32_t xA1 = (tig < 3) ? pack_f16(vx1.x, vx1.y) : 0u;
        const uint32_t xB0 = (tig < 3) ? pack_f16(vx2.x, vx2.y) : 0u;
        const uint32_t xB1 = (tig < 3) ? pack_f16(vx3.x, vx3.y) : 0u;

        // ---- layer 1: m16n8k8, two n-tiles interleaved ----
        #pragma unroll
        for (int tp = 0; tp < 8; tp++) {
            const int t0 = 2 * tp, t1 = 2 * tp + 1;
            const int jc0 = 8 * t0 + 2 * tig;
            const int jc1 = 8 * t1 + 2 * tig;
            const uint32_t b0 = pk1[t0 * 32];
            const uint32_t b1v = pk1[t1 * 32];
            float cA0[4], cB0[4], cA1[4], cB1[4];
            cA0[0] = cA0[2] = cB0[0] = cB0[2] = sB1[jc0];
            cA0[1] = cA0[3] = cB0[1] = cB0[3] = sB1[jc0 + 1];
            cA1[0] = cA1[2] = cB1[0] = cB1[2] = sB1[jc1];
            cA1[1] = cA1[3] = cB1[1] = cB1[3] = sB1[jc1 + 1];
            mma_f16k8(cA0, xA0, xA1, b0);
            mma_f16k8(cB0, xB0, xB1, b0);
            mma_f16k8(cA1, xA0, xA1, b1v);
            mma_f16k8(cB1, xB0, xB1, b1v);
            pack_tile(aA, t0, cA0);
            pack_tile(aB, t0, cB0);
            pack_tile(aA, t1, cA1);
            pack_tile(aB, t1, cB1);
        }

        // ---- layer 2 ----
        #pragma unroll
        for (int tp = 0; tp < 8; tp++)
            hidden_tile_pair(aA, aB, pk2, tp, sB2, tig, aA2, aB2);

        // ---- prefetch next tile's x (covered by L3+L4 latency) ----
        {
            const int nt = tile + gridDim.x;
            if (nt < ntiles && tig < 3) {
                const int nb = nt * TILE_M;
                vx0 = *(const float2*)(x + (nb + pw + g)      * 6 + xk0);
                vx1 = *(const float2*)(x + (nb + pw + g + 8)  * 6 + xk0);
                vx2 = *(const float2*)(x + (nb + pw + g + 16) * 6 + xk0);
                vx3 = *(const float2*)(x + (nb + pw + g + 24) * 6 + xk0);
            }
        }

        // ---- layer 3 (packs back into aA/aB) ----
        #pragma unroll
        for (int tp = 0; tp < 8; tp++)
            hidden_tile_pair(aA2, aB2, pk3, tp, sB3, tig, aA, aB);

        // ---- layer 4: n=8 (4 valid), accumulate 8 k-tiles ----
        {
            float cA[4], cB[4];
            const float bb0 = (tig < 2) ? sB4[2 * tig]     : 0.f;
            const float bb1 = (tig < 2) ? sB4[2 * tig + 1] : 0.f;
            cA[0] = cA[2] = cB[0] = cB[2] = bb0;
            cA[1] = cA[3] = cB[1] = cB[3] = bb1;
            #pragma unroll
            for (int K = 0; K < 8; K++) {
                uint2 b = pk4[K * 32];
                mma_f16(cA, aA + 4 * K, b.x, b.y);
                mma_f16(cB, aB + 4 * K, b.x, b.y);
            }
            if (tig < 2) {
                float* o0 = out + (base + pw + g)      * 4 + 2 * tig;
                float* o1 = out + (base + pw + g + 8)  * 4 + 2 * tig;
                float* o2 = out + (base + pw + g + 16) * 4 + 2 * tig;
                float* o3 = out + (base + pw + g + 24) * 4 + 2 * tig;
                *(float2*)o0 = make_float2(cA[0], cA[1]);
                *(float2*)o1 = make_float2(cA[2], cA[3]);
                *(float2*)o2 = make_float2(cB[0], cB[1]);
                *(float2*)o3 = make_float2(cB[2], cB[3]);
            }
        }
        // no per-tile shared state -> no barriers
    }
}

extern "C" void kernel_launch(void* const* d_in, const int* in_sizes, int n_in,
                              void* d_out, int out_size)
{
    const float* x  = (const float*)d_in[0];
    const float* W1 = (const float*)d_in[1];
    const float* b1 = (const float*)d_in[2];
    const float* W2 = (const float*)d_in[3];
    const float* b2 = (const float*)d_in[4];
    const float* W3 = (const float*)d_in[5];
    const float* b3 = (const float*)d_in[6];
    const float* W4 = (const float*)d_in[7];
    const float* b4 = (const float*)d_in[8];
    float* out = (float*)d_out;

    const int n = in_sizes[0] / 6;
    const int ntiles = n / TILE_M;          // 4096

    // Persistent grid = actual SM count (GB300: 152). Never exceed it:
    // at 1 CTA/SM, extra CTAs serialize.
    static int sm_count = 0;
    if (sm_count == 0) {
        int dev = 0;
        cudaGetDevice(&dev);
        cudaDeviceGetAttribute(&sm_count, cudaDevAttrMultiProcessorCount, dev);
        if (sm_count <= 0) sm_count = 148;
    }
    int grid = sm_count;
    if (grid > ntiles) grid = ntiles;

    cudaFuncSetAttribute(nerf_mma_kernel,
                         cudaFuncAttributeMaxDynamicSharedMemorySize, SMEM_TOTAL);
    nerf_mma_kernel<<<grid, NTHR, SMEM_TOTAL>>>(
        x, W1, b1, W2, b2, W3, b3, W4, b4, out, ntiles);
}